// round 14
// baseline (speedup 1.0000x reference)
#include <cuda_runtime.h>
#include <cuda_bf16.h>
#include <math.h>
#include <stdint.h>

#define B_    2
#define N_    2048
#define F_    1024
#define HID_  1024
#define HEAD_ 16
#define DH_   64
#define MLP_  4096
#define TOK   (B_*N_)     // 4096
#define KPF   (3*F_)      // 3072  (split-bf16 tripled K / row stride)
#define KPM   (3*MLP_)    // 12288
#define KQKV  (2*F_)      // 2048  (2-term split K-extent for QKV)

// ---------------- static scratch (allocation-free) ----------------
__device__ float g_OUT[(size_t)TOK*F_];
// bf16 Q/K/V (Q pre-scaled by 1/sqrt(HID))
__device__ __nv_bfloat16 g_Qh [(size_t)TOK*HID_];
__device__ __nv_bfloat16 g_Kh [(size_t)TOK*HID_];
__device__ __nv_bfloat16 g_Vh [(size_t)TOK*HID_];
// bf16-split activations, layout per row: [hi(K) | lo(K) | hi(K)]
__device__ __nv_bfloat16 g_H3 [(size_t)TOK*KPF];
__device__ __nv_bfloat16 g_A3 [(size_t)TOK*KPF];
__device__ __nv_bfloat16 g_H23[(size_t)TOK*KPF];
__device__ __nv_bfloat16 g_M13[(size_t)TOK*KPM];
// bf16-split weights, layout per row: [hi(K) | hi(K) | lo(K)]
__device__ __nv_bfloat16 g_Wqkv3[(size_t)3*HID_*KPF];   // merged QKV (only [hi|hi] used)
__device__ __nv_bfloat16 g_Wo3[(size_t)F_*KPF];
__device__ __nv_bfloat16 g_W13[(size_t)MLP_*KPF];
__device__ __nv_bfloat16 g_W23[(size_t)F_*KPM];

// ---------------- helpers ----------------
__device__ __forceinline__ uint32_t smem_u32(const void* p) {
    uint32_t a;
    asm("{ .reg .u64 t; cvta.to.shared.u64 t, %1; cvt.u32.u64 %0, t; }" : "=r"(a) : "l"(p));
    return a;
}
__device__ __forceinline__ float gelu_exact(float x) {
    return 0.5f * x * (1.0f + erff(x * 0.70710678118654752f));
}
__device__ __forceinline__ void split_bf16(float v, __nv_bfloat16& hi, __nv_bfloat16& lo) {
    hi = __float2bfloat16(v);
    lo = __float2bfloat16(v - __bfloat162float(hi));
}
__device__ __forceinline__ uint32_t packbf(float lo_val, float hi_val) {
    uint32_t r;
    asm("cvt.rn.bf16x2.f32 %0, %1, %2;" : "=r"(r) : "f"(hi_val), "f"(lo_val));
    return r;
}
__device__ __forceinline__ float block_sum(float v, float* red, int tid) {
    #pragma unroll
    for (int o = 16; o; o >>= 1) v += __shfl_xor_sync(0xffffffffu, v, o);
    if ((tid & 31) == 0) red[tid >> 5] = v;
    __syncthreads();
    if (tid < 32) {
        float t = (tid < 8) ? red[tid] : 0.0f;
        #pragma unroll
        for (int o = 4; o; o >>= 1) t += __shfl_xor_sync(0xffffffffu, t, o);
        if (tid == 0) red[0] = t;
    }
    __syncthreads();
    float r = red[0];
    __syncthreads();
    return r;
}

#define CP16(saddr, gptr) \
    asm volatile("cp.async.cg.shared.global [%0], [%1], 16;" \
        :: "r"(saddr), "l"(gptr) : "memory")
#define CP_COMMIT() asm volatile("cp.async.commit_group;" ::: "memory")
#define CP_WAIT0()  asm volatile("cp.async.wait_group 0;" ::: "memory")

#define LDMX4(r0,r1,r2,r3, addr) \
    asm volatile("ldmatrix.sync.aligned.m8n8.x4.shared.b16 {%0,%1,%2,%3}, [%4];" \
        : "=r"(r0), "=r"(r1), "=r"(r2), "=r"(r3) : "r"(addr))
#define LDMX2(r0,r1, addr) \
    asm volatile("ldmatrix.sync.aligned.m8n8.x2.shared.b16 {%0,%1}, [%2];" \
        : "=r"(r0), "=r"(r1) : "r"(addr))
#define LDMX2T(r0,r1, addr) \
    asm volatile("ldmatrix.sync.aligned.m8n8.x2.trans.shared.b16 {%0,%1}, [%2];" \
        : "=r"(r0), "=r"(r1) : "r"(addr))
#define MMA16816(d0,d1,d2,d3, a0,a1,a2,a3, b0,b1) \
    asm volatile("mma.sync.aligned.m16n8k16.row.col.f32.bf16.bf16.f32 " \
        "{%0,%1,%2,%3}, {%4,%5,%6,%7}, {%8,%9}, {%0,%1,%2,%3};" \
        : "+f"(d0), "+f"(d1), "+f"(d2), "+f"(d3) \
        : "r"(a0), "r"(a1), "r"(a2), "r"(a3), "r"(b0), "r"(b1))

// ---------------- weight conversion ----------------
// merged QKV: rows 0..1023 Wq, 1024..2047 Wk, 2048..3071 Wv; only [hi|hi] needed
__global__ void conv_qkv(const float* __restrict__ Wq, const float* __restrict__ Wk,
                         const float* __restrict__ Wv) {
    int id = blockIdx.x * 256 + threadIdx.x;
    int row = id >> 8;            // F_/4 = 256 quads per row
    int c   = (id & 255) * 4;
    const float* src = (row < 1024) ? Wq : (row < 2048) ? Wk : Wv;
    int srow = row & 1023;
    float4 w = *reinterpret_cast<const float4*>(src + (size_t)srow * F_ + c);
    __nv_bfloat162 hA, hB;
    hA.x = __float2bfloat16(w.x); hA.y = __float2bfloat16(w.y);
    hB.x = __float2bfloat16(w.z); hB.y = __float2bfloat16(w.w);
    __nv_bfloat16* r0 = g_Wqkv3 + (size_t)row * KPF + c;
    *reinterpret_cast<__nv_bfloat162*>(r0)          = hA;
    *reinterpret_cast<__nv_bfloat162*>(r0 + 2)      = hB;
    *reinterpret_cast<__nv_bfloat162*>(r0 + F_)     = hA;
    *reinterpret_cast<__nv_bfloat162*>(r0 + F_ + 2) = hB;
}

// 3-term weights merged: Wo (1024xK1024), W1 (4096xK1024), W2 (1024xK4096)
// quad id ranges: Wo [0,262144), W1 [262144,1310720), W2 [1310720,2359296)
__global__ void conv_w3(const float* __restrict__ Wo, const float* __restrict__ W1,
                        const float* __restrict__ W2) {
    int id = blockIdx.x * 256 + threadIdx.x;
    const float* src;
    __nv_bfloat16* dst;
    int row, c, KK;
    if (id < 262144) {
        src = Wo; dst = g_Wo3; KK = 1024;
        row = id >> 8; c = (id & 255) * 4;
    } else if (id < 1310720) {
        int t = id - 262144;
        src = W1; dst = g_W13; KK = 1024;
        row = t >> 8; c = (t & 255) * 4;
    } else {
        int t = id - 1310720;
        src = W2; dst = g_W23; KK = 4096;
        row = t >> 10; c = (t & 1023) * 4;
    }
    float4 w = *reinterpret_cast<const float4*>(src + (size_t)row * KK + c);
    __nv_bfloat16 h0,h1,h2,h3,l0,l1,l2,l3;
    split_bf16(w.x,h0,l0); split_bf16(w.y,h1,l1);
    split_bf16(w.z,h2,l2); split_bf16(w.w,h3,l3);
    __nv_bfloat16* r0 = dst + (size_t)row * (3*KK) + c;
    __nv_bfloat162 hA; hA.x=h0; hA.y=h1;
    __nv_bfloat162 hB; hB.x=h2; hB.y=h3;
    __nv_bfloat162 lA; lA.x=l0; lA.y=l1;
    __nv_bfloat162 lB; lB.x=l2; lB.y=l3;
    *reinterpret_cast<__nv_bfloat162*>(r0)            = hA;
    *reinterpret_cast<__nv_bfloat162*>(r0 + 2)        = hB;
    *reinterpret_cast<__nv_bfloat162*>(r0 + KK)       = hA;
    *reinterpret_cast<__nv_bfloat162*>(r0 + KK + 2)   = hB;
    *reinterpret_cast<__nv_bfloat162*>(r0 + 2*KK)     = lA;
    *reinterpret_cast<__nv_bfloat162*>(r0 + 2*KK + 2) = lB;
}

// ---------------- LayerNorm -> bf16 triple [hi|lo|hi] ----------------------
template<int LN>
__global__ void ln_wrap(const float* __restrict__ x, const float* __restrict__ g,
                        const float* __restrict__ b) {
    __shared__ float red[8];
    int row = blockIdx.x;
    int tid = threadIdx.x;
    const float* src = (LN == 1) ? x : g_OUT;
    __nv_bfloat16* dst = (LN == 1) ? g_H3 : g_H23;

    float4 v = reinterpret_cast<const float4*>(src + (size_t)row * F_)[tid];
    float s = v.x + v.y + v.z + v.w;
    float mean = block_sum(s, red, tid) * (1.0f / F_);
    float dx = v.x - mean, dy = v.y - mean, dz = v.z - mean, dw = v.w - mean;
    float ss = dx*dx + dy*dy + dz*dz + dw*dw;
    float var = block_sum(ss, red, tid) * (1.0f / F_);
    float rstd = rsqrtf(var + 1e-5f);
    float4 g4 = reinterpret_cast<const float4*>(g)[tid];
    float4 b4 = reinterpret_cast<const float4*>(b)[tid];
    float o0 = dx * rstd * g4.x + b4.x;
    float o1 = dy * rstd * g4.y + b4.y;
    float o2 = dz * rstd * g4.z + b4.z;
    float o3 = dw * rstd * g4.w + b4.w;

    __nv_bfloat16 h0,h1,h2,h3,l0,l1,l2,l3;
    split_bf16(o0,h0,l0); split_bf16(o1,h1,l1);
    split_bf16(o2,h2,l2); split_bf16(o3,h3,l3);
    __nv_bfloat16* r0 = dst + (size_t)row * KPF + tid * 4;
    __nv_bfloat162 hA; hA.x=h0; hA.y=h1;
    __nv_bfloat162 hB; hB.x=h2; hB.y=h3;
    __nv_bfloat162 lA; lA.x=l0; lA.y=l1;
    __nv_bfloat162 lB; lB.x=l2; lB.y=l3;
    *reinterpret_cast<__nv_bfloat162*>(r0)            = hA;
    *reinterpret_cast<__nv_bfloat162*>(r0 + 2)        = hB;
    *reinterpret_cast<__nv_bfloat162*>(r0 + F_)       = lA;
    *reinterpret_cast<__nv_bfloat162*>(r0 + F_ + 2)   = lB;
    *reinterpret_cast<__nv_bfloat162*>(r0 + 2*F_)     = hA;
    *reinterpret_cast<__nv_bfloat162*>(r0 + 2*F_ + 2) = hB;
}

// ---------------- mma.sync GEMM, cp.async, K-chunk 64, 2-stage (72KB) ------
// CTA 128x128, pitch 72 bf16, 2 CTAs/SM. 4 warps 2x2 -> warp tile 64x64.
// (64x64 warp tile halves ldmatrix traffic per MAC vs 64x32.)
// SRC: 0 g_H3, 1 g_A3, 2 g_H23, 3 g_M13
// WSEL: 6 g_Wqkv3, 3 g_Wo3, 4 g_W13, 5 g_W23
// DST: 0 QKV-merged (bf16 Qh/Kh/Vh by colBase>>10), 3 g_OUT, 4 g_M13 triple, 5 out_ext
// RES: 0 none, 1 res_ext, 2 g_OUT
// KP = K-extent, KS = row stride (KP <= KS)
#define OPBYTES 18432                     // 128*72*2 per operand per stage
#define GSTAGE  (2*OPBYTES)               // 36864
#define GEMM_SMEM (2*GSTAGE)              // 73728
template<int SRC, int WSEL, int DST, int HASBIAS, int ACT, int RES, int NN, int KP, int KS>
__global__ __launch_bounds__(128)
void gemm_mma(const float* __restrict__ bias, const float* __restrict__ res_ext,
              float* __restrict__ out_ext) {
    extern __shared__ char smraw[];
    const __nv_bfloat16* A = (SRC == 0) ? g_H3 : (SRC == 1) ? g_A3 :
                             (SRC == 2) ? g_H23 : g_M13;
    const __nv_bfloat16* W = (WSEL == 6) ? g_Wqkv3 : (WSEL == 3) ? g_Wo3 :
                             (WSEL == 4) ? g_W13 : g_W23;

    int tid = threadIdx.x;
    int wid = tid >> 5;        // 0..3
    int lane = tid & 31;
    int rowBase = blockIdx.y * 128;
    int colBase = blockIdx.x * 128;
    int mrow = (wid >> 1) * 64;    // warp M offset (2 warp-rows)
    int ncol = (wid & 1) * 64;     // warp N offset (2 warp-cols)
    constexpr int NC = KP / 64;

    uint32_t sbase = smem_u32(smraw);
    uint32_t aOff = (uint32_t)(((mrow + (lane & 15)) * 72 + (lane >> 4) * 8) * 2);
    uint32_t bOff = (uint32_t)(((ncol + (lane & 7)) * 72 + ((lane >> 3) & 1) * 8) * 2);

    float acc[4][8][4];
    #pragma unroll
    for (int mt = 0; mt < 4; mt++)
        #pragma unroll
        for (int nt = 0; nt < 8; nt++)
            #pragma unroll
            for (int k = 0; k < 4; k++) acc[mt][nt][k] = 0.0f;

    // cp.async chunk loader: 128 rows x 64 bf16 per operand, pitch 72
    auto load_chunk = [&](int j, int st) {
        size_t k0 = (size_t)j * 64;
        uint32_t base = sbase + st * GSTAGE;
        #pragma unroll
        for (int id = tid; id < 1024; id += 128) {
            int row = id >> 3, seg = id & 7;
            CP16(base + (row * 72 + seg * 8) * 2,
                 A + (size_t)(rowBase + row) * KS + k0 + seg * 8);
        }
        #pragma unroll
        for (int id = tid; id < 1024; id += 128) {
            int row = id >> 3, seg = id & 7;
            CP16(base + OPBYTES + (row * 72 + seg * 8) * 2,
                 W + (size_t)(colBase + row) * KS + k0 + seg * 8);
        }
        CP_COMMIT();
    };

    load_chunk(0, 0);

    for (int j = 0; j < NC; j++) {
        int st = j & 1;
        CP_WAIT0();
        __syncthreads();
        if (j + 1 < NC) load_chunk(j + 1, st ^ 1);

        uint32_t ab = sbase + st * GSTAGE + aOff;
        uint32_t bb = sbase + st * GSTAGE + OPBYTES + bOff;
        #pragma unroll
        for (int kk = 0; kk < 4; kk++) {
            uint32_t ko = kk * 32;   // 16 bf16 = 32 bytes
            uint32_t a[4][4], bf[8][2];
            #pragma unroll
            for (int mt = 0; mt < 4; mt++)
                LDMX4(a[mt][0], a[mt][1], a[mt][2], a[mt][3], ab + mt * 2304 + ko);
            #pragma unroll
            for (int nt = 0; nt < 8; nt++)
                LDMX2(bf[nt][0], bf[nt][1], bb + nt * 1152 + ko);
            #pragma unroll
            for (int mt = 0; mt < 4; mt++)
                #pragma unroll
                for (int nt = 0; nt < 8; nt++)
                    MMA16816(acc[mt][nt][0], acc[mt][nt][1], acc[mt][nt][2], acc[mt][nt][3],
                             a[mt][0], a[mt][1], a[mt][2], a[mt][3],
                             bf[nt][0], bf[nt][1]);
        }
    }

    // ---------------- epilogue ----------------
    #pragma unroll
    for (int mt = 0; mt < 4; mt++) {
        #pragma unroll
        for (int nt = 0; nt < 8; nt++) {
            int cc = colBase + ncol + nt * 8 + (lane & 3) * 2;
            float b0 = 0.0f, b1 = 0.0f;
            if (HASBIAS) { b0 = bias[cc]; b1 = bias[cc + 1]; }
            #pragma unroll
            for (int h = 0; h < 2; h++) {
                int r = rowBase + mrow + mt * 16 + (lane >> 2) + h * 8;
                float v0 = acc[mt][nt][h * 2 + 0] + b0;
                float v1 = acc[mt][nt][h * 2 + 1] + b1;
                if (ACT == 1) { v0 = gelu_exact(v0); v1 = gelu_exact(v1); }
                if (RES != 0) {
                    const float* rp = ((RES == 1) ? res_ext : g_OUT) + (size_t)r * NN + cc;
                    float2 rv = *reinterpret_cast<const float2*>(rp);
                    v0 += rv.x; v1 += rv.y;
                }
                if (DST == 0) {
                    // merged QKV: tile column block selects Q/K/V
                    int sel = colBase >> 10;
                    __nv_bfloat16* Ch = (sel == 0) ? g_Qh : (sel == 1) ? g_Kh : g_Vh;
                    const float sc = (sel == 0) ? 0.03125f : 1.0f;
                    int ccl = cc & 1023;
                    __nv_bfloat162 p;
                    p.x = __float2bfloat16(v0 * sc);
                    p.y = __float2bfloat16(v1 * sc);
                    *reinterpret_cast<__nv_bfloat162*>(Ch + (size_t)r * HID_ + ccl) = p;
                } else if (DST != 4) {
                    float* Cc = (DST == 3) ? g_OUT : out_ext;
                    float2 w2; w2.x = v0; w2.y = v1;
                    *reinterpret_cast<float2*>(Cc + (size_t)r * NN + cc) = w2;
                } else {
                    __nv_bfloat16 h0, h1, l0, l1;
                    split_bf16(v0, h0, l0);
                    split_bf16(v1, h1, l1);
                    __nv_bfloat162 hp; hp.x = h0; hp.y = h1;
                    __nv_bfloat162 lp; lp.x = l0; lp.y = l1;
                    __nv_bfloat16* mp = g_M13 + (size_t)r * KPM + cc;
                    *reinterpret_cast<__nv_bfloat162*>(mp)            = hp;
                    *reinterpret_cast<__nv_bfloat162*>(mp + MLP_)     = lp;
                    *reinterpret_cast<__nv_bfloat162*>(mp + 2*MLP_)   = hp;
                }
            }
        }
    }
}

// ---------------- Flash attention (mma.sync, cp.async double-buffered K/V) --
__global__ __launch_bounds__(128)
void attn_mma() {
    __shared__ __nv_bfloat16 Qs[64*72];
    __shared__ __nv_bfloat16 Ks[2][64*72];
    __shared__ __nv_bfloat16 Vs[2][64*72];

    int tid = threadIdx.x;
    int wid = tid >> 5;
    int lane = tid & 31;
    int bh = blockIdx.y;
    int b  = bh >> 4;
    int h  = bh & 15;
    int qbase = blockIdx.x * 64;

    const __nv_bfloat16* kbase = g_Kh + (size_t)b * N_ * HID_ + h * DH_;
    const __nv_bfloat16* vbase = g_Vh + (size_t)b * N_ * HID_ + h * DH_;

    uint32_t kb0 = smem_u32(&Ks[0][0]);
    uint32_t vb0 = smem_u32(&Vs[0][0]);

    auto loadKV = [&](int t, int st) {
        int t0 = t * 64;
        uint32_t kba = kb0 + st * 9216;
        uint32_t vba = vb0 + st * 9216;
        #pragma unroll
        for (int id = tid; id < 512; id += 128) {
            int row = id >> 3, seg = id & 7;
            uint32_t so = (uint32_t)((row * 72 + seg * 8) * 2);
            CP16(kba + so, kbase + (size_t)(t0 + row) * HID_ + seg * 8);
            CP16(vba + so, vbase + (size_t)(t0 + row) * HID_ + seg * 8);
        }
        CP_COMMIT();
    };

    loadKV(0, 0);

    {
        const __nv_bfloat16* qsrc = g_Qh + ((size_t)b * N_ + qbase) * HID_ + h * DH_;
        #pragma unroll
        for (int id = tid; id < 512; id += 128) {
            int row = id >> 3, seg = id & 7;
            *reinterpret_cast<uint4*>(&Qs[row * 72 + seg * 8]) =
                *reinterpret_cast<const uint4*>(qsrc + (size_t)row * HID_ + seg * 8);
        }
    }
    __syncthreads();

    uint32_t qb = smem_u32(Qs);

    uint32_t aq[4][4];
    #pragma unroll
    for (int kc = 0; kc < 4; kc++)
        LDMX4(aq[kc][0], aq[kc][1], aq[kc][2], aq[kc][3],
              qb + ((wid * 16 + (lane & 15)) * 72 + kc * 16 + (lane >> 4) * 8) * 2);

    float m0 = -INFINITY, m1 = -INFINITY, l0 = 0.0f, l1 = 0.0f;
    float o[8][4];
    #pragma unroll
    for (int dt = 0; dt < 8; dt++)
        #pragma unroll
        for (int k = 0; k < 4; k++) o[dt][k] = 0.0f;

    for (int t = 0; t < N_/64; t++) {
        int st = t & 1;
        CP_WAIT0();
        __syncthreads();
        if (t + 1 < N_/64) loadKV(t + 1, st ^ 1);

        uint32_t kb = kb0 + st * 9216;
        uint32_t vb = vb0 + st * 9216;

        float s[8][4];
        #pragma unroll
        for (int nt = 0; nt < 8; nt++)
            #pragma unroll
            for (int k = 0; k < 4; k++) s[nt][k] = 0.0f;
        #pragma unroll
        for (int kc = 0; kc < 4; kc++) {
            #pragma unroll
            for (int nt = 0; nt < 8; nt++) {
                uint32_t bk0, bk1;
                LDMX2(bk0, bk1, kb + ((nt * 8 + (lane & 7)) * 72 + kc * 16 + ((lane >> 3) & 1) * 8) * 2);
                MMA16816(s[nt][0], s[nt][1], s[nt][2], s[nt][3],
                         aq[kc][0], aq[kc][1], aq[kc][2], aq[kc][3], bk0, bk1);
            }
        }

        float mt0 = -INFINITY, mt1 = -INFINITY;
        #pragma unroll
        for (int nt = 0; nt < 8; nt++) {
            mt0 = fmaxf(mt0, fmaxf(s[nt][0], s[nt][1]));
            mt1 = fmaxf(mt1, fmaxf(s[nt][2], s[nt][3]));
        }
        mt0 = fmaxf(mt0, __shfl_xor_sync(0xffffffffu, mt0, 1));
        mt0 = fmaxf(mt0, __shfl_xor_sync(0xffffffffu, mt0, 2));
        mt1 = fmaxf(mt1, __shfl_xor_sync(0xffffffffu, mt1, 1));
        mt1 = fmaxf(mt1, __shfl_xor_sync(0xffffffffu, mt1, 2));
        float mn0 = fmaxf(m0, mt0), mn1 = fmaxf(m1, mt1);
        float al0 = __expf(m0 - mn0), al1 = __expf(m1 - mn1);

        float ls0 = 0.0f, ls1 = 0.0f;
        #pragma unroll
        for (int nt = 0; nt < 8; nt++) {
            s[nt][0] = __expf(s[nt][0] - mn0);
            s[nt][1] = __expf(s[nt][1] - mn0);
            s[nt][2] = __expf(s[nt][2] - mn1);
            s[nt][3] = __expf(s[nt][3] - mn1);
            ls0 += s[nt][0] + s[nt][1];
            ls1 += s[nt][2] + s[nt][3];
        }
        ls0 += __shfl_xor_sync(0xffffffffu, ls0, 1);
        ls0 += __shfl_xor_sync(0xffffffffu, ls0, 2);
        ls1 += __shfl_xor_sync(0xffffffffu, ls1, 1);
        ls1 += __shfl_xor_sync(0xffffffffu, ls1, 2);
        l0 = l0 * al0 + ls0;
        l1 = l1 * al1 + ls1;
        m0 = mn0; m1 = mn1;
        #pragma unroll
        for (int dt = 0; dt < 8; dt++) {
            o[dt][0] *= al0; o[dt][1] *= al0;
            o[dt][2] *= al1; o[dt][3] *= al1;
        }

        uint32_t pa[4][4];
        #pragma unroll
        for (int kc = 0; kc < 4; kc++) {
            pa[kc][0] = packbf(s[2*kc][0],   s[2*kc][1]);
            pa[kc][1] = packbf(s[2*kc][2],   s[2*kc][3]);
            pa[kc][2] = packbf(s[2*kc+1][0], s[2*kc+1][1]);
            pa[kc][3] = packbf(s[2*kc+1][2], s[2*kc+1][3]);
        }

        #pragma unroll
        for (int kc = 0; kc < 4; kc++) {
            #pragma unroll
            for (int dt = 0; dt < 8; dt++) {
                uint32_t bv0, bv1;
                LDMX2T(bv0, bv1, vb + ((kc * 16 + (lane & 15)) * 72 + dt * 8) * 2);
                MMA16816(o[dt][0], o[dt][1], o[dt][2], o[dt][3],
                         pa[kc][0], pa[kc][1], pa[kc][2], pa[kc][3], bv0, bv1);
            }
        }
    }

    float li0 = 1.0f / l0, li1 = 1.0f / l1;
    int r0 = qbase + wid * 16 + (lane >> 2);
    __nv_bfloat16* arow0 = g_A3 + ((size_t)b * N_ + r0) * KPF;
    __nv_bfloat16* arow1 = arow0 + (size_t)8 * KPF;
    #pragma unroll
    for (int dt = 0; dt < 8; dt++) {
        int col = h * DH_ + dt * 8 + (lane & 3) * 2;
        {
            float v0 = o[dt][0] * li0, v1 = o[dt][1] * li0;
            __nv_bfloat16 h0, h1, lo0, lo1;
            split_bf16(v0, h0, lo0); split_bf16(v1, h1, lo1);
            __nv_bfloat162 hp; hp.x = h0; hp.y = h1;
            __nv_bfloat162 lp; lp.x = lo0; lp.y = lo1;
            *reinterpret_cast<__nv_bfloat162*>(arow0 + col)            = hp;
            *reinterpret_cast<__nv_bfloat162*>(arow0 + HID_ + col)     = lp;
            *reinterpret_cast<__nv_bfloat162*>(arow0 + 2*HID_ + col)   = hp;
        }
        {
            float v2 = o[dt][2] * li1, v3 = o[dt][3] * li1;
            __nv_bfloat16 h2, h3, lo2, lo3;
            split_bf16(v2, h2, lo2); split_bf16(v3, h3, lo3);
            __nv_bfloat162 hp; hp.x = h2; hp.y = h3;
            __nv_bfloat162 lp; lp.x = lo2; lp.y = lo3;
            *reinterpret_cast<__nv_bfloat162*>(arow1 + col)            = hp;
            *reinterpret_cast<__nv_bfloat162*>(arow1 + HID_ + col)     = lp;
            *reinterpret_cast<__nv_bfloat162*>(arow1 + 2*HID_ + col)   = hp;
        }
    }
}

// ---------------- launch ----------------
extern "C" void kernel_launch(void* const* d_in, const int* in_sizes, int n_in,
                              void* d_out, int out_size) {
    const float* x     = (const float*)d_in[0];
    const float* la1_g = (const float*)d_in[1];
    const float* la1_b = (const float*)d_in[2];
    const float* Wq    = (const float*)d_in[3];
    const float* Wk    = (const float*)d_in[4];
    const float* Wv    = (const float*)d_in[5];
    const float* Wo    = (const float*)d_in[6];
    const float* bo    = (const float*)d_in[7];
    const float* la2_g = (const float*)d_in[8];
    const float* la2_b = (const float*)d_in[9];
    const float* W1    = (const float*)d_in[10];
    const float* b1    = (const float*)d_in[11];
    const float* W2    = (const float*)d_in[12];
    const float* b2    = (const float*)d_in[13];
    float* out = (float*)d_out;

    cudaFuncSetAttribute(gemm_mma<0,6,0,0,0,0,HID_,KQKV,KPF>, cudaFuncAttributeMaxDynamicSharedMemorySize, GEMM_SMEM);
    cudaFuncSetAttribute(gemm_mma<1,3,3,1,0,1,F_,KPF,KPF>,    cudaFuncAttributeMaxDynamicSharedMemorySize, GEMM_SMEM);
    cudaFuncSetAttribute(gemm_mma<2,4,4,1,1,0,MLP_,KPF,KPF>,  cudaFuncAttributeMaxDynamicSharedMemorySize, GEMM_SMEM);
    cudaFuncSetAttribute(gemm_mma<3,5,5,1,1,2,F_,KPM,KPM>,    cudaFuncAttributeMaxDynamicSharedMemorySize, GEMM_SMEM);

    // 0. weight conversion (2 kernels: QKV hi|hi, merged 3-term Wo/W1/W2)
    conv_qkv<<<3*HID_*F_/4/256, 256>>>(Wq, Wk, Wv);
    conv_w3<<<9216, 256>>>(Wo, W1, W2);

    // 1. LN1: x -> g_H3 (triple)
    ln_wrap<1><<<TOK, 256>>>(x, la1_g, la1_b);

    // 2. merged QKV projection (2-term split, K=2048): -> g_Qh/g_Kh/g_Vh
    gemm_mma<0,6,0,0,0,0,HID_,KQKV,KPF><<<dim3(3*HID_/128, TOK/128), 128, GEMM_SMEM>>>(nullptr, nullptr, nullptr);

    // 3. attention (tensor cores, cp.async): -> g_A3 (triple)
    attn_mma<<<dim3(N_/64, B_*HEAD_), 128>>>();

    // 4. output projection + bias + residual(x): g_A3 -> g_OUT (fp32)
    gemm_mma<1,3,3,1,0,1,F_,KPF,KPF><<<dim3(F_/128, TOK/128), 128, GEMM_SMEM>>>(bo, x, nullptr);

    // 5. LN2: g_OUT -> g_H23 (triple)
    ln_wrap<2><<<TOK, 256>>>(nullptr, la2_g, la2_b);

    // 6. MLP up + GELU: g_H23 -> g_M13 (triple, fused split)
    gemm_mma<2,4,4,1,1,0,MLP_,KPF,KPF><<<dim3(MLP_/128, TOK/128), 128, GEMM_SMEM>>>(b1, nullptr, nullptr);

    // 7. MLP down + GELU + residual(g_OUT): g_M13 -> out (fp32)
    gemm_mma<3,5,5,1,1,2,F_,KPM,KPM><<<dim3(F_/128, TOK/128), 128, GEMM_SMEM>>>(b2, nullptr, out);
}

// round 16
// speedup vs baseline: 1.8090x; 1.8090x over previous
#include <cuda_runtime.h>
#include <cuda_bf16.h>
#include <math.h>
#include <stdint.h>

#define B_    2
#define N_    2048
#define F_    1024
#define HID_  1024
#define HEAD_ 16
#define DH_   64
#define MLP_  4096
#define TOK   (B_*N_)     // 4096
#define KPF   (3*F_)      // 3072  (split-bf16 tripled K / row stride)
#define KPM   (3*MLP_)    // 12288
#define KQKV  (2*F_)      // 2048  (2-term split K-extent for QKV)

// ---------------- static scratch (allocation-free) ----------------
__device__ float g_OUT[(size_t)TOK*F_];
// bf16 Q/K/V (Q pre-scaled by 1/sqrt(HID))
__device__ __nv_bfloat16 g_Qh [(size_t)TOK*HID_];
__device__ __nv_bfloat16 g_Kh [(size_t)TOK*HID_];
__device__ __nv_bfloat16 g_Vh [(size_t)TOK*HID_];
// bf16-split activations, layout per row: [hi(K) | lo(K) | hi(K)]
__device__ __nv_bfloat16 g_H3 [(size_t)TOK*KPF];
__device__ __nv_bfloat16 g_A3 [(size_t)TOK*KPF];
__device__ __nv_bfloat16 g_H23[(size_t)TOK*KPF];
__device__ __nv_bfloat16 g_M13[(size_t)TOK*KPM];
// bf16-split weights, layout per row: [hi(K) | hi(K) | lo(K)]
__device__ __nv_bfloat16 g_Wqkv3[(size_t)3*HID_*KPF];   // merged QKV (only [hi|hi] used)
__device__ __nv_bfloat16 g_Wo3[(size_t)F_*KPF];
__device__ __nv_bfloat16 g_W13[(size_t)MLP_*KPF];
__device__ __nv_bfloat16 g_W23[(size_t)F_*KPM];

// ---------------- helpers ----------------
__device__ __forceinline__ uint32_t smem_u32(const void* p) {
    uint32_t a;
    asm("{ .reg .u64 t; cvta.to.shared.u64 t, %1; cvt.u32.u64 %0, t; }" : "=r"(a) : "l"(p));
    return a;
}
__device__ __forceinline__ float gelu_exact(float x) {
    return 0.5f * x * (1.0f + erff(x * 0.70710678118654752f));
}
__device__ __forceinline__ void split_bf16(float v, __nv_bfloat16& hi, __nv_bfloat16& lo) {
    hi = __float2bfloat16(v);
    lo = __float2bfloat16(v - __bfloat162float(hi));
}
__device__ __forceinline__ uint32_t packbf(float lo_val, float hi_val) {
    uint32_t r;
    asm("cvt.rn.bf16x2.f32 %0, %1, %2;" : "=r"(r) : "f"(hi_val), "f"(lo_val));
    return r;
}
__device__ __forceinline__ float block_sum(float v, float* red, int tid) {
    #pragma unroll
    for (int o = 16; o; o >>= 1) v += __shfl_xor_sync(0xffffffffu, v, o);
    if ((tid & 31) == 0) red[tid >> 5] = v;
    __syncthreads();
    if (tid < 32) {
        float t = (tid < 8) ? red[tid] : 0.0f;
        #pragma unroll
        for (int o = 4; o; o >>= 1) t += __shfl_xor_sync(0xffffffffu, t, o);
        if (tid == 0) red[0] = t;
    }
    __syncthreads();
    float r = red[0];
    __syncthreads();
    return r;
}

#define CP16(saddr, gptr) \
    asm volatile("cp.async.cg.shared.global [%0], [%1], 16;" \
        :: "r"(saddr), "l"(gptr) : "memory")
#define CP_COMMIT() asm volatile("cp.async.commit_group;" ::: "memory")
#define CP_WAIT0()  asm volatile("cp.async.wait_group 0;" ::: "memory")
#define CP_WAIT1()  asm volatile("cp.async.wait_group 1;" ::: "memory")

#define LDMX4(r0,r1,r2,r3, addr) \
    asm volatile("ldmatrix.sync.aligned.m8n8.x4.shared.b16 {%0,%1,%2,%3}, [%4];" \
        : "=r"(r0), "=r"(r1), "=r"(r2), "=r"(r3) : "r"(addr))
#define LDMX2(r0,r1, addr) \
    asm volatile("ldmatrix.sync.aligned.m8n8.x2.shared.b16 {%0,%1}, [%2];" \
        : "=r"(r0), "=r"(r1) : "r"(addr))
#define LDMX2T(r0,r1, addr) \
    asm volatile("ldmatrix.sync.aligned.m8n8.x2.trans.shared.b16 {%0,%1}, [%2];" \
        : "=r"(r0), "=r"(r1) : "r"(addr))
#define MMA16816(d0,d1,d2,d3, a0,a1,a2,a3, b0,b1) \
    asm volatile("mma.sync.aligned.m16n8k16.row.col.f32.bf16.bf16.f32 " \
        "{%0,%1,%2,%3}, {%4,%5,%6,%7}, {%8,%9}, {%0,%1,%2,%3};" \
        : "+f"(d0), "+f"(d1), "+f"(d2), "+f"(d3) \
        : "r"(a0), "r"(a1), "r"(a2), "r"(a3), "r"(b0), "r"(b1))

// ---------------- weight conversion ----------------
// merged QKV: rows 0..1023 Wq, 1024..2047 Wk, 2048..3071 Wv; only [hi|hi] needed
__global__ void conv_qkv(const float* __restrict__ Wq, const float* __restrict__ Wk,
                         const float* __restrict__ Wv) {
    int id = blockIdx.x * 256 + threadIdx.x;
    int row = id >> 8;            // F_/4 = 256 quads per row
    int c   = (id & 255) * 4;
    const float* src = (row < 1024) ? Wq : (row < 2048) ? Wk : Wv;
    int srow = row & 1023;
    float4 w = *reinterpret_cast<const float4*>(src + (size_t)srow * F_ + c);
    __nv_bfloat162 hA, hB;
    hA.x = __float2bfloat16(w.x); hA.y = __float2bfloat16(w.y);
    hB.x = __float2bfloat16(w.z); hB.y = __float2bfloat16(w.w);
    __nv_bfloat16* r0 = g_Wqkv3 + (size_t)row * KPF + c;
    *reinterpret_cast<__nv_bfloat162*>(r0)          = hA;
    *reinterpret_cast<__nv_bfloat162*>(r0 + 2)      = hB;
    *reinterpret_cast<__nv_bfloat162*>(r0 + F_)     = hA;
    *reinterpret_cast<__nv_bfloat162*>(r0 + F_ + 2) = hB;
}

// 3-term weights merged: Wo (1024xK1024), W1 (4096xK1024), W2 (1024xK4096)
__global__ void conv_w3(const float* __restrict__ Wo, const float* __restrict__ W1,
                        const float* __restrict__ W2) {
    int id = blockIdx.x * 256 + threadIdx.x;
    const float* src;
    __nv_bfloat16* dst;
    int row, c, KK;
    if (id < 262144) {
        src = Wo; dst = g_Wo3; KK = 1024;
        row = id >> 8; c = (id & 255) * 4;
    } else if (id < 1310720) {
        int t = id - 262144;
        src = W1; dst = g_W13; KK = 1024;
        row = t >> 8; c = (t & 255) * 4;
    } else {
        int t = id - 1310720;
        src = W2; dst = g_W23; KK = 4096;
        row = t >> 10; c = (t & 1023) * 4;
    }
    float4 w = *reinterpret_cast<const float4*>(src + (size_t)row * KK + c);
    __nv_bfloat16 h0,h1,h2,h3,l0,l1,l2,l3;
    split_bf16(w.x,h0,l0); split_bf16(w.y,h1,l1);
    split_bf16(w.z,h2,l2); split_bf16(w.w,h3,l3);
    __nv_bfloat16* r0 = dst + (size_t)row * (3*KK) + c;
    __nv_bfloat162 hA; hA.x=h0; hA.y=h1;
    __nv_bfloat162 hB; hB.x=h2; hB.y=h3;
    __nv_bfloat162 lA; lA.x=l0; lA.y=l1;
    __nv_bfloat162 lB; lB.x=l2; lB.y=l3;
    *reinterpret_cast<__nv_bfloat162*>(r0)            = hA;
    *reinterpret_cast<__nv_bfloat162*>(r0 + 2)        = hB;
    *reinterpret_cast<__nv_bfloat162*>(r0 + KK)       = hA;
    *reinterpret_cast<__nv_bfloat162*>(r0 + KK + 2)   = hB;
    *reinterpret_cast<__nv_bfloat162*>(r0 + 2*KK)     = lA;
    *reinterpret_cast<__nv_bfloat162*>(r0 + 2*KK + 2) = lB;
}

// ---------------- LayerNorm -> bf16 triple [hi|lo|hi] ----------------------
template<int LN>
__global__ void ln_wrap(const float* __restrict__ x, const float* __restrict__ g,
                        const float* __restrict__ b) {
    __shared__ float red[8];
    int row = blockIdx.x;
    int tid = threadIdx.x;
    const float* src = (LN == 1) ? x : g_OUT;
    __nv_bfloat16* dst = (LN == 1) ? g_H3 : g_H23;

    float4 v = reinterpret_cast<const float4*>(src + (size_t)row * F_)[tid];
    float s = v.x + v.y + v.z + v.w;
    float mean = block_sum(s, red, tid) * (1.0f / F_);
    float dx = v.x - mean, dy = v.y - mean, dz = v.z - mean, dw = v.w - mean;
    float ss = dx*dx + dy*dy + dz*dz + dw*dw;
    float var = block_sum(ss, red, tid) * (1.0f / F_);
    float rstd = rsqrtf(var + 1e-5f);
    float4 g4 = reinterpret_cast<const float4*>(g)[tid];
    float4 b4 = reinterpret_cast<const float4*>(b)[tid];
    float o0 = dx * rstd * g4.x + b4.x;
    float o1 = dy * rstd * g4.y + b4.y;
    float o2 = dz * rstd * g4.z + b4.z;
    float o3 = dw * rstd * g4.w + b4.w;

    __nv_bfloat16 h0,h1,h2,h3,l0,l1,l2,l3;
    split_bf16(o0,h0,l0); split_bf16(o1,h1,l1);
    split_bf16(o2,h2,l2); split_bf16(o3,h3,l3);
    __nv_bfloat16* r0 = dst + (size_t)row * KPF + tid * 4;
    __nv_bfloat162 hA; hA.x=h0; hA.y=h1;
    __nv_bfloat162 hB; hB.x=h2; hB.y=h3;
    __nv_bfloat162 lA; lA.x=l0; lA.y=l1;
    __nv_bfloat162 lB; lB.x=l2; lB.y=l3;
    *reinterpret_cast<__nv_bfloat162*>(r0)            = hA;
    *reinterpret_cast<__nv_bfloat162*>(r0 + 2)        = hB;
    *reinterpret_cast<__nv_bfloat162*>(r0 + F_)       = lA;
    *reinterpret_cast<__nv_bfloat162*>(r0 + F_ + 2)   = lB;
    *reinterpret_cast<__nv_bfloat162*>(r0 + 2*F_)     = hA;
    *reinterpret_cast<__nv_bfloat162*>(r0 + 2*F_ + 2) = hB;
}

// ---------------- mma.sync GEMM, cp.async, K-chunk 64, 3-stage swizzled ----
// CTA 128x128, SW128 XOR swizzle (no padding): stage = 2x16KB, 3 stages = 96KB.
// 8 warps 2x4 -> warp tile 64x32 (round-13 proven config), 2 CTAs/SM.
// SRC: 0 g_H3, 1 g_A3, 2 g_H23, 3 g_M13
// WSEL: 6 g_Wqkv3, 3 g_Wo3, 4 g_W13, 5 g_W23
// DST: 0 QKV-merged (bf16 Qh/Kh/Vh by colBase>>10), 3 g_OUT, 4 g_M13 triple, 5 out_ext
// RES: 0 none, 1 res_ext, 2 g_OUT
// KP = K-extent, KS = row stride (KP <= KS)
#define OPBYTES 16384                     // 128 rows * 128B, swizzled
#define GSTAGE  (2*OPBYTES)               // 32768
#define GEMM_SMEM (3*GSTAGE)              // 98304
template<int SRC, int WSEL, int DST, int HASBIAS, int ACT, int RES, int NN, int KP, int KS>
__global__ __launch_bounds__(256, 2)
void gemm_mma(const float* __restrict__ bias, const float* __restrict__ res_ext,
              float* __restrict__ out_ext) {
    extern __shared__ char smraw[];
    const __nv_bfloat16* A = (SRC == 0) ? g_H3 : (SRC == 1) ? g_A3 :
                             (SRC == 2) ? g_H23 : g_M13;
    const __nv_bfloat16* W = (WSEL == 6) ? g_Wqkv3 : (WSEL == 3) ? g_Wo3 :
                             (WSEL == 4) ? g_W13 : g_W23;

    int tid = threadIdx.x;
    int wid = tid >> 5;
    int lane = tid & 31;
    int rowBase = blockIdx.y * 128;
    int colBase = blockIdx.x * 128;
    int mrow = (wid & 1) * 64;
    int ncol = (wid >> 1) * 32;
    constexpr int NC = KP / 64;

    uint32_t sbase = smem_u32(smraw);
    // swizzled ldmatrix lane addressing: byte = row*128 + ((col16) ^ ((row&7)<<4))
    uint32_t aRow    = (uint32_t)(mrow + (lane & 15));
    uint32_t aRowOff = aRow * 128;
    uint32_t aXor    = (aRow & 7) << 4;
    uint32_t aHalf   = (uint32_t)(lane >> 4) * 16;
    uint32_t bRow    = (uint32_t)(ncol + (lane & 7));
    uint32_t bRowOff = bRow * 128;
    uint32_t bXor    = (bRow & 7) << 4;
    uint32_t bHalf   = (uint32_t)((lane >> 3) & 1) * 16;

    float acc[4][4][4];
    #pragma unroll
    for (int mt = 0; mt < 4; mt++)
        #pragma unroll
        for (int nt = 0; nt < 4; nt++)
            #pragma unroll
            for (int k = 0; k < 4; k++) acc[mt][nt][k] = 0.0f;

    // cp.async chunk loader: 128 rows x 64 bf16 (128B) per operand, swizzled
    auto load_chunk = [&](int j, int st) {
        size_t k0 = (size_t)j * 64;
        uint32_t base = sbase + st * GSTAGE;
        #pragma unroll
        for (int id = tid; id < 1024; id += 256) {
            int row = id >> 3, seg = id & 7;
            CP16(base + row * 128 + ((uint32_t)(seg ^ (row & 7)) << 4),
                 A + (size_t)(rowBase + row) * KS + k0 + seg * 8);
        }
        #pragma unroll
        for (int id = tid; id < 1024; id += 256) {
            int row = id >> 3, seg = id & 7;
            CP16(base + OPBYTES + row * 128 + ((uint32_t)(seg ^ (row & 7)) << 4),
                 W + (size_t)(colBase + row) * KS + k0 + seg * 8);
        }
        CP_COMMIT();
    };

    load_chunk(0, 0);
    load_chunk(1, 1);

    int st = 0, pf = 2;
    for (int j = 0; j < NC; j++) {
        if (j + 1 < NC) CP_WAIT1(); else CP_WAIT0();
        __syncthreads();
        if (j + 2 < NC) load_chunk(j + 2, pf);

        uint32_t ab = sbase + st * GSTAGE;
        uint32_t bb = ab + OPBYTES;
        #pragma unroll
        for (int kk = 0; kk < 4; kk++) {
            uint32_t aCol = ((uint32_t)(kk * 32) + aHalf) ^ aXor;
            uint32_t bCol = ((uint32_t)(kk * 32) + bHalf) ^ bXor;
            uint32_t a[4][4], bf[4][2];
            #pragma unroll
            for (int mt = 0; mt < 4; mt++)
                LDMX4(a[mt][0], a[mt][1], a[mt][2], a[mt][3],
                      ab + aRowOff + mt * 2048 + aCol);
            #pragma unroll
            for (int nt = 0; nt < 4; nt++)
                LDMX2(bf[nt][0], bf[nt][1], bb + bRowOff + nt * 1024 + bCol);
            #pragma unroll
            for (int mt = 0; mt < 4; mt++)
                #pragma unroll
                for (int nt = 0; nt < 4; nt++)
                    MMA16816(acc[mt][nt][0], acc[mt][nt][1], acc[mt][nt][2], acc[mt][nt][3],
                             a[mt][0], a[mt][1], a[mt][2], a[mt][3],
                             bf[nt][0], bf[nt][1]);
        }
        st = (st == 2) ? 0 : st + 1;
        pf = (pf == 2) ? 0 : pf + 1;
    }

    // ---------------- epilogue ----------------
    #pragma unroll
    for (int mt = 0; mt < 4; mt++) {
        #pragma unroll
        for (int nt = 0; nt < 4; nt++) {
            int cc = colBase + ncol + nt * 8 + (lane & 3) * 2;
            float b0 = 0.0f, b1 = 0.0f;
            if (HASBIAS) { b0 = bias[cc]; b1 = bias[cc + 1]; }
            #pragma unroll
            for (int h = 0; h < 2; h++) {
                int r = rowBase + mrow + mt * 16 + (lane >> 2) + h * 8;
                float v0 = acc[mt][nt][h * 2 + 0] + b0;
                float v1 = acc[mt][nt][h * 2 + 1] + b1;
                if (ACT == 1) { v0 = gelu_exact(v0); v1 = gelu_exact(v1); }
                if (RES != 0) {
                    const float* rp = ((RES == 1) ? res_ext : g_OUT) + (size_t)r * NN + cc;
                    float2 rv = *reinterpret_cast<const float2*>(rp);
                    v0 += rv.x; v1 += rv.y;
                }
                if (DST == 0) {
                    // merged QKV: tile column block selects Q/K/V
                    int sel = colBase >> 10;
                    __nv_bfloat16* Ch = (sel == 0) ? g_Qh : (sel == 1) ? g_Kh : g_Vh;
                    const float sc = (sel == 0) ? 0.03125f : 1.0f;
                    int ccl = cc & 1023;
                    __nv_bfloat162 p;
                    p.x = __float2bfloat16(v0 * sc);
                    p.y = __float2bfloat16(v1 * sc);
                    *reinterpret_cast<__nv_bfloat162*>(Ch + (size_t)r * HID_ + ccl) = p;
                } else if (DST != 4) {
                    float* Cc = (DST == 3) ? g_OUT : out_ext;
                    float2 w2; w2.x = v0; w2.y = v1;
                    *reinterpret_cast<float2*>(Cc + (size_t)r * NN + cc) = w2;
                } else {
                    __nv_bfloat16 h0, h1, l0, l1;
                    split_bf16(v0, h0, l0);
                    split_bf16(v1, h1, l1);
                    __nv_bfloat162 hp; hp.x = h0; hp.y = h1;
                    __nv_bfloat162 lp; lp.x = l0; lp.y = l1;
                    __nv_bfloat16* mp = g_M13 + (size_t)r * KPM + cc;
                    *reinterpret_cast<__nv_bfloat162*>(mp)            = hp;
                    *reinterpret_cast<__nv_bfloat162*>(mp + MLP_)     = lp;
                    *reinterpret_cast<__nv_bfloat162*>(mp + 2*MLP_)   = hp;
                }
            }
        }
    }
}

// ---------------- Flash attention (mma.sync, cp.async double-buffered K/V) --
__global__ __launch_bounds__(128)
void attn_mma() {
    __shared__ __nv_bfloat16 Qs[64*72];
    __shared__ __nv_bfloat16 Ks[2][64*72];
    __shared__ __nv_bfloat16 Vs[2][64*72];

    int tid = threadIdx.x;
    int wid = tid >> 5;
    int lane = tid & 31;
    int bh = blockIdx.y;
    int b  = bh >> 4;
    int h  = bh & 15;
    int qbase = blockIdx.x * 64;

    const __nv_bfloat16* kbase = g_Kh + (size_t)b * N_ * HID_ + h * DH_;
    const __nv_bfloat16* vbase = g_Vh + (size_t)b * N_ * HID_ + h * DH_;

    uint32_t kb0 = smem_u32(&Ks[0][0]);
    uint32_t vb0 = smem_u32(&Vs[0][0]);

    auto loadKV = [&](int t, int st) {
        int t0 = t * 64;
        uint32_t kba = kb0 + st * 9216;
        uint32_t vba = vb0 + st * 9216;
        #pragma unroll
        for (int id = tid; id < 512; id += 128) {
            int row = id >> 3, seg = id & 7;
            uint32_t so = (uint32_t)((row * 72 + seg * 8) * 2);
            CP16(kba + so, kbase + (size_t)(t0 + row) * HID_ + seg * 8);
            CP16(vba + so, vbase + (size_t)(t0 + row) * HID_ + seg * 8);
        }
        CP_COMMIT();
    };

    loadKV(0, 0);

    {
        const __nv_bfloat16* qsrc = g_Qh + ((size_t)b * N_ + qbase) * HID_ + h * DH_;
        #pragma unroll
        for (int id = tid; id < 512; id += 128) {
            int row = id >> 3, seg = id & 7;
            *reinterpret_cast<uint4*>(&Qs[row * 72 + seg * 8]) =
                *reinterpret_cast<const uint4*>(qsrc + (size_t)row * HID_ + seg * 8);
        }
    }
    __syncthreads();

    uint32_t qb = smem_u32(Qs);

    uint32_t aq[4][4];
    #pragma unroll
    for (int kc = 0; kc < 4; kc++)
        LDMX4(aq[kc][0], aq[kc][1], aq[kc][2], aq[kc][3],
              qb + ((wid * 16 + (lane & 15)) * 72 + kc * 16 + (lane >> 4) * 8) * 2);

    float m0 = -INFINITY, m1 = -INFINITY, l0 = 0.0f, l1 = 0.0f;
    float o[8][4];
    #pragma unroll
    for (int dt = 0; dt < 8; dt++)
        #pragma unroll
        for (int k = 0; k < 4; k++) o[dt][k] = 0.0f;

    for (int t = 0; t < N_/64; t++) {
        int st = t & 1;
        CP_WAIT0();
        __syncthreads();
        if (t + 1 < N_/64) loadKV(t + 1, st ^ 1);

        uint32_t kb = kb0 + st * 9216;
        uint32_t vb = vb0 + st * 9216;

        float s[8][4];
        #pragma unroll
        for (int nt = 0; nt < 8; nt++)
            #pragma unroll
            for (int k = 0; k < 4; k++) s[nt][k] = 0.0f;
        #pragma unroll
        for (int kc = 0; kc < 4; kc++) {
            #pragma unroll
            for (int nt = 0; nt < 8; nt++) {
                uint32_t bk0, bk1;
                LDMX2(bk0, bk1, kb + ((nt * 8 + (lane & 7)) * 72 + kc * 16 + ((lane >> 3) & 1) * 8) * 2);
                MMA16816(s[nt][0], s[nt][1], s[nt][2], s[nt][3],
                         aq[kc][0], aq[kc][1], aq[kc][2], aq[kc][3], bk0, bk1);
            }
        }

        float mt0 = -INFINITY, mt1 = -INFINITY;
        #pragma unroll
        for (int nt = 0; nt < 8; nt++) {
            mt0 = fmaxf(mt0, fmaxf(s[nt][0], s[nt][1]));
            mt1 = fmaxf(mt1, fmaxf(s[nt][2], s[nt][3]));
        }
        mt0 = fmaxf(mt0, __shfl_xor_sync(0xffffffffu, mt0, 1));
        mt0 = fmaxf(mt0, __shfl_xor_sync(0xffffffffu, mt0, 2));
        mt1 = fmaxf(mt1, __shfl_xor_sync(0xffffffffu, mt1, 1));
        mt1 = fmaxf(mt1, __shfl_xor_sync(0xffffffffu, mt1, 2));
        float mn0 = fmaxf(m0, mt0), mn1 = fmaxf(m1, mt1);
        float al0 = __expf(m0 - mn0), al1 = __expf(m1 - mn1);

        float ls0 = 0.0f, ls1 = 0.0f;
        #pragma unroll
        for (int nt = 0; nt < 8; nt++) {
            s[nt][0] = __expf(s[nt][0] - mn0);
            s[nt][1] = __expf(s[nt][1] - mn0);
            s[nt][2] = __expf(s[nt][2] - mn1);
            s[nt][3] = __expf(s[nt][3] - mn1);
            ls0 += s[nt][0] + s[nt][1];
            ls1 += s[nt][2] + s[nt][3];
        }
        ls0 += __shfl_xor_sync(0xffffffffu, ls0, 1);
        ls0 += __shfl_xor_sync(0xffffffffu, ls0, 2);
        ls1 += __shfl_xor_sync(0xffffffffu, ls1, 1);
        ls1 += __shfl_xor_sync(0xffffffffu, ls1, 2);
        l0 = l0 * al0 + ls0;
        l1 = l1 * al1 + ls1;
        m0 = mn0; m1 = mn1;
        #pragma unroll
        for (int dt = 0; dt < 8; dt++) {
            o[dt][0] *= al0; o[dt][1] *= al0;
            o[dt][2] *= al1; o[dt][3] *= al1;
        }

        uint32_t pa[4][4];
        #pragma unroll
        for (int kc = 0; kc < 4; kc++) {
            pa[kc][0] = packbf(s[2*kc][0],   s[2*kc][1]);
            pa[kc][1] = packbf(s[2*kc][2],   s[2*kc][3]);
            pa[kc][2] = packbf(s[2*kc+1][0], s[2*kc+1][1]);
            pa[kc][3] = packbf(s[2*kc+1][2], s[2*kc+1][3]);
        }

        #pragma unroll
        for (int kc = 0; kc < 4; kc++) {
            #pragma unroll
            for (int dt = 0; dt < 8; dt++) {
                uint32_t bv0, bv1;
                LDMX2T(bv0, bv1, vb + ((kc * 16 + (lane & 15)) * 72 + dt * 8) * 2);
                MMA16816(o[dt][0], o[dt][1], o[dt][2], o[dt][3],
                         pa[kc][0], pa[kc][1], pa[kc][2], pa[kc][3], bv0, bv1);
            }
        }
    }

    float li0 = 1.0f / l0, li1 = 1.0f / l1;
    int r0 = qbase + wid * 16 + (lane >> 2);
    __nv_bfloat16* arow0 = g_A3 + ((size_t)b * N_ + r0) * KPF;
    __nv_bfloat16* arow1 = arow0 + (size_t)8 * KPF;
    #pragma unroll
    for (int dt = 0; dt < 8; dt++) {
        int col = h * DH_ + dt * 8 + (lane & 3) * 2;
        {
            float v0 = o[dt][0] * li0, v1 = o[dt][1] * li0;
            __nv_bfloat16 h0, h1, lo0, lo1;
            split_bf16(v0, h0, lo0); split_bf16(v1, h1, lo1);
            __nv_bfloat162 hp; hp.x = h0; hp.y = h1;
            __nv_bfloat162 lp; lp.x = lo0; lp.y = lo1;
            *reinterpret_cast<__nv_bfloat162*>(arow0 + col)            = hp;
            *reinterpret_cast<__nv_bfloat162*>(arow0 + HID_ + col)     = lp;
            *reinterpret_cast<__nv_bfloat162*>(arow0 + 2*HID_ + col)   = hp;
        }
        {
            float v2 = o[dt][2] * li1, v3 = o[dt][3] * li1;
            __nv_bfloat16 h2, h3, lo2, lo3;
            split_bf16(v2, h2, lo2); split_bf16(v3, h3, lo3);
            __nv_bfloat162 hp; hp.x = h2; hp.y = h3;
            __nv_bfloat162 lp; lp.x = lo2; lp.y = lo3;
            *reinterpret_cast<__nv_bfloat162*>(arow1 + col)            = hp;
            *reinterpret_cast<__nv_bfloat162*>(arow1 + HID_ + col)     = lp;
            *reinterpret_cast<__nv_bfloat162*>(arow1 + 2*HID_ + col)   = hp;
        }
    }
}

// ---------------- launch ----------------
extern "C" void kernel_launch(void* const* d_in, const int* in_sizes, int n_in,
                              void* d_out, int out_size) {
    const float* x     = (const float*)d_in[0];
    const float* la1_g = (const float*)d_in[1];
    const float* la1_b = (const float*)d_in[2];
    const float* Wq    = (const float*)d_in[3];
    const float* Wk    = (const float*)d_in[4];
    const float* Wv    = (const float*)d_in[5];
    const float* Wo    = (const float*)d_in[6];
    const float* bo    = (const float*)d_in[7];
    const float* la2_g = (const float*)d_in[8];
    const float* la2_b = (const float*)d_in[9];
    const float* W1    = (const float*)d_in[10];
    const float* b1    = (const float*)d_in[11];
    const float* W2    = (const float*)d_in[12];
    const float* b2    = (const float*)d_in[13];
    float* out = (float*)d_out;

    cudaFuncSetAttribute(gemm_mma<0,6,0,0,0,0,HID_,KQKV,KPF>, cudaFuncAttributeMaxDynamicSharedMemorySize, GEMM_SMEM);
    cudaFuncSetAttribute(gemm_mma<1,3,3,1,0,1,F_,KPF,KPF>,    cudaFuncAttributeMaxDynamicSharedMemorySize, GEMM_SMEM);
    cudaFuncSetAttribute(gemm_mma<2,4,4,1,1,0,MLP_,KPF,KPF>,  cudaFuncAttributeMaxDynamicSharedMemorySize, GEMM_SMEM);
    cudaFuncSetAttribute(gemm_mma<3,5,5,1,1,2,F_,KPM,KPM>,    cudaFuncAttributeMaxDynamicSharedMemorySize, GEMM_SMEM);

    // 0. weight conversion
    conv_qkv<<<3*HID_*F_/4/256, 256>>>(Wq, Wk, Wv);
    conv_w3<<<9216, 256>>>(Wo, W1, W2);

    // 1. LN1: x -> g_H3 (triple)
    ln_wrap<1><<<TOK, 256>>>(x, la1_g, la1_b);

    // 2. merged QKV projection (2-term split, K=2048): -> g_Qh/g_Kh/g_Vh
    gemm_mma<0,6,0,0,0,0,HID_,KQKV,KPF><<<dim3(3*HID_/128, TOK/128), 256, GEMM_SMEM>>>(nullptr, nullptr, nullptr);

    // 3. attention (tensor cores, cp.async): -> g_A3 (triple)
    attn_mma<<<dim3(N_/64, B_*HEAD_), 128>>>();

    // 4. output projection + bias + residual(x): g_A3 -> g_OUT (fp32)
    gemm_mma<1,3,3,1,0,1,F_,KPF,KPF><<<dim3(F_/128, TOK/128), 256, GEMM_SMEM>>>(bo, x, nullptr);

    // 5. LN2: g_OUT -> g_H23 (triple)
    ln_wrap<2><<<TOK, 256>>>(nullptr, la2_g, la2_b);

    // 6. MLP up + GELU: g_H23 -> g_M13 (triple, fused split)
    gemm_mma<2,4,4,1,1,0,MLP_,KPF,KPF><<<dim3(MLP_/128, TOK/128), 256, GEMM_SMEM>>>(b1, nullptr, nullptr);

    // 7. MLP down + GELU + residual(g_OUT): g_M13 -> out (fp32)
    gemm_mma<3,5,5,1,1,2,F_,KPM,KPM><<<dim3(F_/128, TOK/128), 256, GEMM_SMEM>>>(b2, nullptr, out);
}

// round 17
// speedup vs baseline: 1.8867x; 1.0429x over previous
#include <cuda_runtime.h>
#include <cuda_bf16.h>
#include <math.h>
#include <stdint.h>

#define B_    2
#define N_    2048
#define F_    1024
#define HID_  1024
#define HEAD_ 16
#define DH_   64
#define MLP_  4096
#define TOK   (B_*N_)     // 4096
#define AS2   (2*F_)      // 2048: activation [hi|lo] stride
#define MS2   (2*MLP_)    // 8192: MLP activation [hi|lo] stride

// ---------------- static scratch (allocation-free, dedup layouts) ----------
__device__ float g_OUT[(size_t)TOK*F_];
// bf16 Q/K/V (Q pre-scaled by 1/sqrt(HID))
__device__ __nv_bfloat16 g_Qh [(size_t)TOK*HID_];
__device__ __nv_bfloat16 g_Kh [(size_t)TOK*HID_];
__device__ __nv_bfloat16 g_Vh [(size_t)TOK*HID_];
// split activations, per row [hi(K) | lo(K)]
__device__ __nv_bfloat16 g_H3 [(size_t)TOK*AS2];
__device__ __nv_bfloat16 g_A3 [(size_t)TOK*AS2];
__device__ __nv_bfloat16 g_H23[(size_t)TOK*AS2];
__device__ __nv_bfloat16 g_M13[(size_t)TOK*MS2];
// split weights, per row [hi(K) | lo(K)]; QKV: hi only
__device__ __nv_bfloat16 g_Wqkv[(size_t)3*HID_*F_];
__device__ __nv_bfloat16 g_Wo3[(size_t)F_*AS2];
__device__ __nv_bfloat16 g_W13[(size_t)MLP_*AS2];
__device__ __nv_bfloat16 g_W23[(size_t)F_*MS2];

// ---------------- helpers ----------------
__device__ __forceinline__ uint32_t smem_u32(const void* p) {
    uint32_t a;
    asm("{ .reg .u64 t; cvta.to.shared.u64 t, %1; cvt.u32.u64 %0, t; }" : "=r"(a) : "l"(p));
    return a;
}
__device__ __forceinline__ float gelu_exact(float x) {
    return 0.5f * x * (1.0f + erff(x * 0.70710678118654752f));
}
__device__ __forceinline__ void split_bf16(float v, __nv_bfloat16& hi, __nv_bfloat16& lo) {
    hi = __float2bfloat16(v);
    lo = __float2bfloat16(v - __bfloat162float(hi));
}
__device__ __forceinline__ uint32_t packbf(float lo_val, float hi_val) {
    uint32_t r;
    asm("cvt.rn.bf16x2.f32 %0, %1, %2;" : "=r"(r) : "f"(hi_val), "f"(lo_val));
    return r;
}
__device__ __forceinline__ float block_sum(float v, float* red, int tid) {
    #pragma unroll
    for (int o = 16; o; o >>= 1) v += __shfl_xor_sync(0xffffffffu, v, o);
    if ((tid & 31) == 0) red[tid >> 5] = v;
    __syncthreads();
    if (tid < 32) {
        float t = (tid < 8) ? red[tid] : 0.0f;
        #pragma unroll
        for (int o = 4; o; o >>= 1) t += __shfl_xor_sync(0xffffffffu, t, o);
        if (tid == 0) red[0] = t;
    }
    __syncthreads();
    float r = red[0];
    __syncthreads();
    return r;
}

#define CP16(saddr, gptr) \
    asm volatile("cp.async.cg.shared.global [%0], [%1], 16;" \
        :: "r"(saddr), "l"(gptr) : "memory")
#define CP_COMMIT() asm volatile("cp.async.commit_group;" ::: "memory")
#define CP_WAIT0()  asm volatile("cp.async.wait_group 0;" ::: "memory")
#define CP_WAIT1()  asm volatile("cp.async.wait_group 1;" ::: "memory")

#define LDMX4(r0,r1,r2,r3, addr) \
    asm volatile("ldmatrix.sync.aligned.m8n8.x4.shared.b16 {%0,%1,%2,%3}, [%4];" \
        : "=r"(r0), "=r"(r1), "=r"(r2), "=r"(r3) : "r"(addr))
#define LDMX2(r0,r1, addr) \
    asm volatile("ldmatrix.sync.aligned.m8n8.x2.shared.b16 {%0,%1}, [%2];" \
        : "=r"(r0), "=r"(r1) : "r"(addr))
#define LDMX2T(r0,r1, addr) \
    asm volatile("ldmatrix.sync.aligned.m8n8.x2.trans.shared.b16 {%0,%1}, [%2];" \
        : "=r"(r0), "=r"(r1) : "r"(addr))
#define MMA16816(d0,d1,d2,d3, a0,a1,a2,a3, b0,b1) \
    asm volatile("mma.sync.aligned.m16n8k16.row.col.f32.bf16.bf16.f32 " \
        "{%0,%1,%2,%3}, {%4,%5,%6,%7}, {%8,%9}, {%0,%1,%2,%3};" \
        : "+f"(d0), "+f"(d1), "+f"(d2), "+f"(d3) \
        : "r"(a0), "r"(a1), "r"(a2), "r"(a3), "r"(b0), "r"(b1))

// ---------------- weight conversion ----------------
// merged QKV: rows 0..1023 Wq, 1024..2047 Wk, 2048..3071 Wv; hi only, stride F_
__global__ void conv_qkv(const float* __restrict__ Wq, const float* __restrict__ Wk,
                         const float* __restrict__ Wv) {
    int id = blockIdx.x * 256 + threadIdx.x;
    int row = id >> 8;            // F_/4 = 256 quads per row
    int c   = (id & 255) * 4;
    const float* src = (row < 1024) ? Wq : (row < 2048) ? Wk : Wv;
    int srow = row & 1023;
    float4 w = *reinterpret_cast<const float4*>(src + (size_t)srow * F_ + c);
    __nv_bfloat162 hA, hB;
    hA.x = __float2bfloat16(w.x); hA.y = __float2bfloat16(w.y);
    hB.x = __float2bfloat16(w.z); hB.y = __float2bfloat16(w.w);
    __nv_bfloat16* r0 = g_Wqkv + (size_t)row * F_ + c;
    *reinterpret_cast<__nv_bfloat162*>(r0)     = hA;
    *reinterpret_cast<__nv_bfloat162*>(r0 + 2) = hB;
}

// split weights [hi|lo] stride 2K: Wo (1024xK1024), W1 (4096xK1024), W2 (1024xK4096)
__global__ void conv_w3(const float* __restrict__ Wo, const float* __restrict__ W1,
                        const float* __restrict__ W2) {
    int id = blockIdx.x * 256 + threadIdx.x;
    const float* src;
    __nv_bfloat16* dst;
    int row, c, KK;
    if (id < 262144) {
        src = Wo; dst = g_Wo3; KK = 1024;
        row = id >> 8; c = (id & 255) * 4;
    } else if (id < 1310720) {
        int t = id - 262144;
        src = W1; dst = g_W13; KK = 1024;
        row = t >> 8; c = (t & 255) * 4;
    } else {
        int t = id - 1310720;
        src = W2; dst = g_W23; KK = 4096;
        row = t >> 10; c = (t & 1023) * 4;
    }
    float4 w = *reinterpret_cast<const float4*>(src + (size_t)row * KK + c);
    __nv_bfloat16 h0,h1,h2,h3,l0,l1,l2,l3;
    split_bf16(w.x,h0,l0); split_bf16(w.y,h1,l1);
    split_bf16(w.z,h2,l2); split_bf16(w.w,h3,l3);
    __nv_bfloat16* r0 = dst + (size_t)row * (2*KK) + c;
    __nv_bfloat162 hA; hA.x=h0; hA.y=h1;
    __nv_bfloat162 hB; hB.x=h2; hB.y=h3;
    __nv_bfloat162 lA; lA.x=l0; lA.y=l1;
    __nv_bfloat162 lB; lB.x=l2; lB.y=l3;
    *reinterpret_cast<__nv_bfloat162*>(r0)          = hA;
    *reinterpret_cast<__nv_bfloat162*>(r0 + 2)      = hB;
    *reinterpret_cast<__nv_bfloat162*>(r0 + KK)     = lA;
    *reinterpret_cast<__nv_bfloat162*>(r0 + KK + 2) = lB;
}

// ---------------- LayerNorm -> bf16 [hi|lo] stride 2048 --------------------
template<int LN>
__global__ void ln_wrap(const float* __restrict__ x, const float* __restrict__ g,
                        const float* __restrict__ b) {
    __shared__ float red[8];
    int row = blockIdx.x;
    int tid = threadIdx.x;
    const float* src = (LN == 1) ? x : g_OUT;
    __nv_bfloat16* dst = (LN == 1) ? g_H3 : g_H23;

    float4 v = reinterpret_cast<const float4*>(src + (size_t)row * F_)[tid];
    float s = v.x + v.y + v.z + v.w;
    float mean = block_sum(s, red, tid) * (1.0f / F_);
    float dx = v.x - mean, dy = v.y - mean, dz = v.z - mean, dw = v.w - mean;
    float ss = dx*dx + dy*dy + dz*dz + dw*dw;
    float var = block_sum(ss, red, tid) * (1.0f / F_);
    float rstd = rsqrtf(var + 1e-5f);
    float4 g4 = reinterpret_cast<const float4*>(g)[tid];
    float4 b4 = reinterpret_cast<const float4*>(b)[tid];
    float o0 = dx * rstd * g4.x + b4.x;
    float o1 = dy * rstd * g4.y + b4.y;
    float o2 = dz * rstd * g4.z + b4.z;
    float o3 = dw * rstd * g4.w + b4.w;

    __nv_bfloat16 h0,h1,h2,h3,l0,l1,l2,l3;
    split_bf16(o0,h0,l0); split_bf16(o1,h1,l1);
    split_bf16(o2,h2,l2); split_bf16(o3,h3,l3);
    __nv_bfloat16* r0 = dst + (size_t)row * AS2 + tid * 4;
    __nv_bfloat162 hA; hA.x=h0; hA.y=h1;
    __nv_bfloat162 hB; hB.x=h2; hB.y=h3;
    __nv_bfloat162 lA; lA.x=l0; lA.y=l1;
    __nv_bfloat162 lB; lB.x=l2; lB.y=l3;
    *reinterpret_cast<__nv_bfloat162*>(r0)          = hA;
    *reinterpret_cast<__nv_bfloat162*>(r0 + 2)      = hB;
    *reinterpret_cast<__nv_bfloat162*>(r0 + F_)     = lA;
    *reinterpret_cast<__nv_bfloat162*>(r0 + F_ + 2) = lB;
}

// ---------------- mma.sync GEMM, cp.async, K-chunk 64, 3-stage swizzled ----
// Dedup segment mapping: A segs (hi,lo,hi), W segs (hi,hi,lo); chunk j ->
//   seg = j/SC, jj = j%SC;  aK0 = jj*64 + (seg==1)*SEGK;  wK0 = jj*64 + (seg==2)*SEGK
// CTA 128x128, SW128 XOR swizzle, 8 warps 2x4 (64x32 warp tile), 2 CTAs/SM.
// SRC: 0 g_H3, 1 g_A3, 2 g_H23, 3 g_M13
// WSEL: 6 g_Wqkv, 3 g_Wo3, 4 g_W13, 5 g_W23
// DST: 0 QKV-merged, 3 g_OUT, 4 g_M13 [hi|lo], 5 out_ext
// RES: 0 none, 1 res_ext, 2 g_OUT
// NSEG: 2 (QKV) or 3; SEGK: segment K; ASR/WSR: row strides of A and W
#define OPBYTES 16384                     // 128 rows * 128B, swizzled
#define GSTAGE  (2*OPBYTES)               // 32768
#define GEMM_SMEM (3*GSTAGE)              // 98304
template<int SRC, int WSEL, int DST, int HASBIAS, int ACT, int RES, int NN,
         int NSEG, int SEGK, int ASR, int WSR>
__global__ __launch_bounds__(256, 2)
void gemm_mma(const float* __restrict__ bias, const float* __restrict__ res_ext,
              float* __restrict__ out_ext) {
    extern __shared__ char smraw[];
    const __nv_bfloat16* A = (SRC == 0) ? g_H3 : (SRC == 1) ? g_A3 :
                             (SRC == 2) ? g_H23 : g_M13;
    const __nv_bfloat16* W = (WSEL == 6) ? g_Wqkv : (WSEL == 3) ? g_Wo3 :
                             (WSEL == 4) ? g_W13 : g_W23;

    int tid = threadIdx.x;
    int wid = tid >> 5;
    int lane = tid & 31;
    int rowBase = blockIdx.y * 128;
    int colBase = blockIdx.x * 128;
    int mrow = (wid & 1) * 64;
    int ncol = (wid >> 1) * 32;
    constexpr int SC = SEGK / 64;
    constexpr int NC = NSEG * SC;

    uint32_t sbase = smem_u32(smraw);
    uint32_t aRow    = (uint32_t)(mrow + (lane & 15));
    uint32_t aRowOff = aRow * 128;
    uint32_t aXor    = (aRow & 7) << 4;
    uint32_t aHalf   = (uint32_t)(lane >> 4) * 16;
    uint32_t bRow    = (uint32_t)(ncol + (lane & 7));
    uint32_t bRowOff = bRow * 128;
    uint32_t bXor    = (bRow & 7) << 4;
    uint32_t bHalf   = (uint32_t)((lane >> 3) & 1) * 16;

    float acc[4][4][4];
    #pragma unroll
    for (int mt = 0; mt < 4; mt++)
        #pragma unroll
        for (int nt = 0; nt < 4; nt++)
            #pragma unroll
            for (int k = 0; k < 4; k++) acc[mt][nt][k] = 0.0f;

    // cp.async chunk loader with dedup segment mapping
    auto load_chunk = [&](int j, int st) {
        int seg = j / SC, jj = j - seg * SC;
        size_t aK0 = (size_t)jj * 64 + ((seg == 1) ? SEGK : 0);
        size_t wK0 = (size_t)jj * 64 + ((seg == 2) ? SEGK : 0);
        uint32_t base = sbase + st * GSTAGE;
        #pragma unroll
        for (int id = tid; id < 1024; id += 256) {
            int row = id >> 3, sg = id & 7;
            CP16(base + row * 128 + ((uint32_t)(sg ^ (row & 7)) << 4),
                 A + (size_t)(rowBase + row) * ASR + aK0 + sg * 8);
        }
        #pragma unroll
        for (int id = tid; id < 1024; id += 256) {
            int row = id >> 3, sg = id & 7;
            CP16(base + OPBYTES + row * 128 + ((uint32_t)(sg ^ (row & 7)) << 4),
                 W + (size_t)(colBase + row) * WSR + wK0 + sg * 8);
        }
        CP_COMMIT();
    };

    load_chunk(0, 0);
    load_chunk(1, 1);

    int st = 0, pf = 2;
    for (int j = 0; j < NC; j++) {
        if (j + 1 < NC) CP_WAIT1(); else CP_WAIT0();
        __syncthreads();
        if (j + 2 < NC) load_chunk(j + 2, pf);

        uint32_t ab = sbase + st * GSTAGE;
        uint32_t bb = ab + OPBYTES;
        #pragma unroll
        for (int kk = 0; kk < 4; kk++) {
            uint32_t aCol = ((uint32_t)(kk * 32) + aHalf) ^ aXor;
            uint32_t bCol = ((uint32_t)(kk * 32) + bHalf) ^ bXor;
            uint32_t a[4][4], bf[4][2];
            #pragma unroll
            for (int mt = 0; mt < 4; mt++)
                LDMX4(a[mt][0], a[mt][1], a[mt][2], a[mt][3],
                      ab + aRowOff + mt * 2048 + aCol);
            #pragma unroll
            for (int nt = 0; nt < 4; nt++)
                LDMX2(bf[nt][0], bf[nt][1], bb + bRowOff + nt * 1024 + bCol);
            #pragma unroll
            for (int mt = 0; mt < 4; mt++)
                #pragma unroll
                for (int nt = 0; nt < 4; nt++)
                    MMA16816(acc[mt][nt][0], acc[mt][nt][1], acc[mt][nt][2], acc[mt][nt][3],
                             a[mt][0], a[mt][1], a[mt][2], a[mt][3],
                             bf[nt][0], bf[nt][1]);
        }
        st = (st == 2) ? 0 : st + 1;
        pf = (pf == 2) ? 0 : pf + 1;
    }

    // ---------------- epilogue ----------------
    #pragma unroll
    for (int mt = 0; mt < 4; mt++) {
        #pragma unroll
        for (int nt = 0; nt < 4; nt++) {
            int cc = colBase + ncol + nt * 8 + (lane & 3) * 2;
            float b0 = 0.0f, b1 = 0.0f;
            if (HASBIAS) { b0 = bias[cc]; b1 = bias[cc + 1]; }
            #pragma unroll
            for (int h = 0; h < 2; h++) {
                int r = rowBase + mrow + mt * 16 + (lane >> 2) + h * 8;
                float v0 = acc[mt][nt][h * 2 + 0] + b0;
                float v1 = acc[mt][nt][h * 2 + 1] + b1;
                if (ACT == 1) { v0 = gelu_exact(v0); v1 = gelu_exact(v1); }
                if (RES != 0) {
                    const float* rp = ((RES == 1) ? res_ext : g_OUT) + (size_t)r * NN + cc;
                    float2 rv = *reinterpret_cast<const float2*>(rp);
                    v0 += rv.x; v1 += rv.y;
                }
                if (DST == 0) {
                    int sel = colBase >> 10;
                    __nv_bfloat16* Ch = (sel == 0) ? g_Qh : (sel == 1) ? g_Kh : g_Vh;
                    const float sc = (sel == 0) ? 0.03125f : 1.0f;
                    int ccl = cc & 1023;
                    __nv_bfloat162 p;
                    p.x = __float2bfloat16(v0 * sc);
                    p.y = __float2bfloat16(v1 * sc);
                    *reinterpret_cast<__nv_bfloat162*>(Ch + (size_t)r * HID_ + ccl) = p;
                } else if (DST != 4) {
                    float* Cc = (DST == 3) ? g_OUT : out_ext;
                    float2 w2; w2.x = v0; w2.y = v1;
                    *reinterpret_cast<float2*>(Cc + (size_t)r * NN + cc) = w2;
                } else {
                    // [hi|lo] into g_M13 (row stride MS2)
                    __nv_bfloat16 h0, h1, l0, l1;
                    split_bf16(v0, h0, l0);
                    split_bf16(v1, h1, l1);
                    __nv_bfloat162 hp; hp.x = h0; hp.y = h1;
                    __nv_bfloat162 lp; lp.x = l0; lp.y = l1;
                    __nv_bfloat16* mp = g_M13 + (size_t)r * MS2 + cc;
                    *reinterpret_cast<__nv_bfloat162*>(mp)         = hp;
                    *reinterpret_cast<__nv_bfloat162*>(mp + MLP_)  = lp;
                }
            }
        }
    }
}

// ---------------- Flash attention (mma.sync, cp.async double-buffered K/V) --
__global__ __launch_bounds__(128)
void attn_mma() {
    __shared__ __nv_bfloat16 Qs[64*72];
    __shared__ __nv_bfloat16 Ks[2][64*72];
    __shared__ __nv_bfloat16 Vs[2][64*72];

    int tid = threadIdx.x;
    int wid = tid >> 5;
    int lane = tid & 31;
    int bh = blockIdx.y;
    int b  = bh >> 4;
    int h  = bh & 15;
    int qbase = blockIdx.x * 64;

    const __nv_bfloat16* kbase = g_Kh + (size_t)b * N_ * HID_ + h * DH_;
    const __nv_bfloat16* vbase = g_Vh + (size_t)b * N_ * HID_ + h * DH_;

    uint32_t kb0 = smem_u32(&Ks[0][0]);
    uint32_t vb0 = smem_u32(&Vs[0][0]);

    auto loadKV = [&](int t, int st) {
        int t0 = t * 64;
        uint32_t kba = kb0 + st * 9216;
        uint32_t vba = vb0 + st * 9216;
        #pragma unroll
        for (int id = tid; id < 512; id += 128) {
            int row = id >> 3, seg = id & 7;
            uint32_t so = (uint32_t)((row * 72 + seg * 8) * 2);
            CP16(kba + so, kbase + (size_t)(t0 + row) * HID_ + seg * 8);
            CP16(vba + so, vbase + (size_t)(t0 + row) * HID_ + seg * 8);
        }
        CP_COMMIT();
    };

    loadKV(0, 0);

    {
        const __nv_bfloat16* qsrc = g_Qh + ((size_t)b * N_ + qbase) * HID_ + h * DH_;
        #pragma unroll
        for (int id = tid; id < 512; id += 128) {
            int row = id >> 3, seg = id & 7;
            *reinterpret_cast<uint4*>(&Qs[row * 72 + seg * 8]) =
                *reinterpret_cast<const uint4*>(qsrc + (size_t)row * HID_ + seg * 8);
        }
    }
    __syncthreads();

    uint32_t qb = smem_u32(Qs);

    uint32_t aq[4][4];
    #pragma unroll
    for (int kc = 0; kc < 4; kc++)
        LDMX4(aq[kc][0], aq[kc][1], aq[kc][2], aq[kc][3],
              qb + ((wid * 16 + (lane & 15)) * 72 + kc * 16 + (lane >> 4) * 8) * 2);

    float m0 = -INFINITY, m1 = -INFINITY, l0 = 0.0f, l1 = 0.0f;
    float o[8][4];
    #pragma unroll
    for (int dt = 0; dt < 8; dt++)
        #pragma unroll
        for (int k = 0; k < 4; k++) o[dt][k] = 0.0f;

    for (int t = 0; t < N_/64; t++) {
        int st = t & 1;
        CP_WAIT0();
        __syncthreads();
        if (t + 1 < N_/64) loadKV(t + 1, st ^ 1);

        uint32_t kb = kb0 + st * 9216;
        uint32_t vb = vb0 + st * 9216;

        float s[8][4];
        #pragma unroll
        for (int nt = 0; nt < 8; nt++)
            #pragma unroll
            for (int k = 0; k < 4; k++) s[nt][k] = 0.0f;
        #pragma unroll
        for (int kc = 0; kc < 4; kc++) {
            #pragma unroll
            for (int nt = 0; nt < 8; nt++) {
                uint32_t bk0, bk1;
                LDMX2(bk0, bk1, kb + ((nt * 8 + (lane & 7)) * 72 + kc * 16 + ((lane >> 3) & 1) * 8) * 2);
                MMA16816(s[nt][0], s[nt][1], s[nt][2], s[nt][3],
                         aq[kc][0], aq[kc][1], aq[kc][2], aq[kc][3], bk0, bk1);
            }
        }

        float mt0 = -INFINITY, mt1 = -INFINITY;
        #pragma unroll
        for (int nt = 0; nt < 8; nt++) {
            mt0 = fmaxf(mt0, fmaxf(s[nt][0], s[nt][1]));
            mt1 = fmaxf(mt1, fmaxf(s[nt][2], s[nt][3]));
        }
        mt0 = fmaxf(mt0, __shfl_xor_sync(0xffffffffu, mt0, 1));
        mt0 = fmaxf(mt0, __shfl_xor_sync(0xffffffffu, mt0, 2));
        mt1 = fmaxf(mt1, __shfl_xor_sync(0xffffffffu, mt1, 1));
        mt1 = fmaxf(mt1, __shfl_xor_sync(0xffffffffu, mt1, 2));
        float mn0 = fmaxf(m0, mt0), mn1 = fmaxf(m1, mt1);
        float al0 = __expf(m0 - mn0), al1 = __expf(m1 - mn1);

        float ls0 = 0.0f, ls1 = 0.0f;
        #pragma unroll
        for (int nt = 0; nt < 8; nt++) {
            s[nt][0] = __expf(s[nt][0] - mn0);
            s[nt][1] = __expf(s[nt][1] - mn0);
            s[nt][2] = __expf(s[nt][2] - mn1);
            s[nt][3] = __expf(s[nt][3] - mn1);
            ls0 += s[nt][0] + s[nt][1];
            ls1 += s[nt][2] + s[nt][3];
        }
        ls0 += __shfl_xor_sync(0xffffffffu, ls0, 1);
        ls0 += __shfl_xor_sync(0xffffffffu, ls0, 2);
        ls1 += __shfl_xor_sync(0xffffffffu, ls1, 1);
        ls1 += __shfl_xor_sync(0xffffffffu, ls1, 2);
        l0 = l0 * al0 + ls0;
        l1 = l1 * al1 + ls1;
        m0 = mn0; m1 = mn1;
        #pragma unroll
        for (int dt = 0; dt < 8; dt++) {
            o[dt][0] *= al0; o[dt][1] *= al0;
            o[dt][2] *= al1; o[dt][3] *= al1;
        }

        uint32_t pa[4][4];
        #pragma unroll
        for (int kc = 0; kc < 4; kc++) {
            pa[kc][0] = packbf(s[2*kc][0],   s[2*kc][1]);
            pa[kc][1] = packbf(s[2*kc][2],   s[2*kc][3]);
            pa[kc][2] = packbf(s[2*kc+1][0], s[2*kc+1][1]);
            pa[kc][3] = packbf(s[2*kc+1][2], s[2*kc+1][3]);
        }

        #pragma unroll
        for (int kc = 0; kc < 4; kc++) {
            #pragma unroll
            for (int dt = 0; dt < 8; dt++) {
                uint32_t bv0, bv1;
                LDMX2T(bv0, bv1, vb + ((kc * 16 + (lane & 15)) * 72 + dt * 8) * 2);
                MMA16816(o[dt][0], o[dt][1], o[dt][2], o[dt][3],
                         pa[kc][0], pa[kc][1], pa[kc][2], pa[kc][3], bv0, bv1);
            }
        }
    }

    // epilogue: [hi|lo] rows into g_A3 (stride AS2)
    float li0 = 1.0f / l0, li1 = 1.0f / l1;
    int r0 = qbase + wid * 16 + (lane >> 2);
    __nv_bfloat16* arow0 = g_A3 + ((size_t)b * N_ + r0) * AS2;
    __nv_bfloat16* arow1 = arow0 + (size_t)8 * AS2;
    #pragma unroll
    for (int dt = 0; dt < 8; dt++) {
        int col = h * DH_ + dt * 8 + (lane & 3) * 2;
        {
            float v0 = o[dt][0] * li0, v1 = o[dt][1] * li0;
            __nv_bfloat16 h0, h1, lo0, lo1;
            split_bf16(v0, h0, lo0); split_bf16(v1, h1, lo1);
            __nv_bfloat162 hp; hp.x = h0; hp.y = h1;
            __nv_bfloat162 lp; lp.x = lo0; lp.y = lo1;
            *reinterpret_cast<__nv_bfloat162*>(arow0 + col)        = hp;
            *reinterpret_cast<__nv_bfloat162*>(arow0 + HID_ + col) = lp;
        }
        {
            float v2 = o[dt][2] * li1, v3 = o[dt][3] * li1;
            __nv_bfloat16 h2, h3, lo2, lo3;
            split_bf16(v2, h2, lo2); split_bf16(v3, h3, lo3);
            __nv_bfloat162 hp; hp.x = h2; hp.y = h3;
            __nv_bfloat162 lp; lp.x = lo2; lp.y = lo3;
            *reinterpret_cast<__nv_bfloat162*>(arow1 + col)        = hp;
            *reinterpret_cast<__nv_bfloat162*>(arow1 + HID_ + col) = lp;
        }
    }
}

// ---------------- launch ----------------
extern "C" void kernel_launch(void* const* d_in, const int* in_sizes, int n_in,
                              void* d_out, int out_size) {
    const float* x     = (const float*)d_in[0];
    const float* la1_g = (const float*)d_in[1];
    const float* la1_b = (const float*)d_in[2];
    const float* Wq    = (const float*)d_in[3];
    const float* Wk    = (const float*)d_in[4];
    const float* Wv    = (const float*)d_in[5];
    const float* Wo    = (const float*)d_in[6];
    const float* bo    = (const float*)d_in[7];
    const float* la2_g = (const float*)d_in[8];
    const float* la2_b = (const float*)d_in[9];
    const float* W1    = (const float*)d_in[10];
    const float* b1    = (const float*)d_in[11];
    const float* W2    = (const float*)d_in[12];
    const float* b2    = (const float*)d_in[13];
    float* out = (float*)d_out;

    // GEMM instantiations: <SRC,WSEL,DST,HASBIAS,ACT,RES,NN, NSEG,SEGK,ASR,WSR>
    cudaFuncSetAttribute(gemm_mma<0,6,0,0,0,0,HID_, 2,F_,AS2,F_>,      cudaFuncAttributeMaxDynamicSharedMemorySize, GEMM_SMEM);
    cudaFuncSetAttribute(gemm_mma<1,3,3,1,0,1,F_,   3,F_,AS2,AS2>,     cudaFuncAttributeMaxDynamicSharedMemorySize, GEMM_SMEM);
    cudaFuncSetAttribute(gemm_mma<2,4,4,1,1,0,MLP_, 3,F_,AS2,AS2>,     cudaFuncAttributeMaxDynamicSharedMemorySize, GEMM_SMEM);
    cudaFuncSetAttribute(gemm_mma<3,5,5,1,1,2,F_,   3,MLP_,MS2,MS2>,   cudaFuncAttributeMaxDynamicSharedMemorySize, GEMM_SMEM);

    // 0. weight conversion
    conv_qkv<<<3*HID_*F_/4/256, 256>>>(Wq, Wk, Wv);
    conv_w3<<<9216, 256>>>(Wo, W1, W2);

    // 1. LN1: x -> g_H3 [hi|lo]
    ln_wrap<1><<<TOK, 256>>>(x, la1_g, la1_b);

    // 2. merged QKV projection (2-term, K=2048 effective): -> g_Qh/g_Kh/g_Vh
    gemm_mma<0,6,0,0,0,0,HID_, 2,F_,AS2,F_><<<dim3(3*HID_/128, TOK/128), 256, GEMM_SMEM>>>(nullptr, nullptr, nullptr);

    // 3. attention: -> g_A3 [hi|lo]
    attn_mma<<<dim3(N_/64, B_*HEAD_), 128>>>();

    // 4. output projection + bias + residual(x): g_A3 -> g_OUT (fp32, 3-term)
    gemm_mma<1,3,3,1,0,1,F_, 3,F_,AS2,AS2><<<dim3(F_/128, TOK/128), 256, GEMM_SMEM>>>(bo, x, nullptr);

    // 5. LN2: g_OUT -> g_H23 [hi|lo]
    ln_wrap<2><<<TOK, 256>>>(nullptr, la2_g, la2_b);

    // 6. MLP up + GELU: g_H23 -> g_M13 [hi|lo] (3-term)
    gemm_mma<2,4,4,1,1,0,MLP_, 3,F_,AS2,AS2><<<dim3(MLP_/128, TOK/128), 256, GEMM_SMEM>>>(b1, nullptr, nullptr);

    // 7. MLP down + GELU + residual(g_OUT): g_M13 -> out (fp32, 3-term)
    gemm_mma<3,5,5,1,1,2,F_, 3,MLP_,MS2,MS2><<<dim3(F_/128, TOK/128), 256, GEMM_SMEM>>>(b2, nullptr, out);
}